// round 4
// baseline (speedup 1.0000x reference)
#include <cuda_runtime.h>
#include <cuda_bf16.h>

#define BATCH  512
#define N_NODE 200
#define C_IN   200
#define HIDDEN 128

// scratch: xw = x @ W1, [BATCH, N_NODE, HIDDEN] fp32 (52.4 MB)
__device__ float g_xw[(size_t)BATCH * N_NODE * HIDDEN];

// ---------------------------------------------------------------------------
// K1: xw = x @ W1.   x viewed as [M=BATCH*N_NODE, 200], W1 [200,128].
// 64x128 tile per CTA, K-step 8, 256 threads, 4x8 register tile per thread.
// ---------------------------------------------------------------------------
__global__ __launch_bounds__(256) void gemm_xw_kernel(
    const float* __restrict__ x, const float* __restrict__ W1)
{
    __shared__ float xs[8 * 68];        // [kk][m], pitch 68 to kill store conflicts
    __shared__ float ws[8 * 128];       // [kk][n]

    const int m0 = blockIdx.x * 64;
    const int t  = threadIdx.x;
    const int tx = t & 15;              // 16 col groups * 8 cols
    const int ty = t >> 4;              // 16 row groups * 4 rows

    float acc[4][8];
#pragma unroll
    for (int r = 0; r < 4; r++)
#pragma unroll
        for (int c = 0; c < 8; c++) acc[r][c] = 0.f;

    for (int k0 = 0; k0 < C_IN; k0 += 8) {
        // x tile: 64 rows x 8 k (coalesced per 8-float row segments)
        {
            int li = t;                  // elem 0..255
            int m = li >> 3, kk = li & 7;
            xs[kk * 68 + m] = x[(size_t)(m0 + m) * C_IN + k0 + kk];
            li = t + 256;
            m = li >> 3; kk = li & 7;
            xs[kk * 68 + m] = x[(size_t)(m0 + m) * C_IN + k0 + kk];
        }
        // W tile: 8 x 128 (fully coalesced)
#pragma unroll
        for (int q = 0; q < 4; q++) {
            int li = t + q * 256;
            int kk = li >> 7, n = li & 127;
            ws[kk * 128 + n] = W1[(k0 + kk) * HIDDEN + n];
        }
        __syncthreads();

#pragma unroll
        for (int kk = 0; kk < 8; kk++) {
            float4 xv = *(const float4*)&xs[kk * 68 + ty * 4];
            float4 wa = *(const float4*)&ws[kk * 128 + tx * 8];
            float4 wb = *(const float4*)&ws[kk * 128 + tx * 8 + 4];
            float xr[4] = {xv.x, xv.y, xv.z, xv.w};
            float wc[8] = {wa.x, wa.y, wa.z, wa.w, wb.x, wb.y, wb.z, wb.w};
#pragma unroll
            for (int r = 0; r < 4; r++)
#pragma unroll
                for (int c = 0; c < 8; c++)
                    acc[r][c] += xr[r] * wc[c];
        }
        __syncthreads();
    }

#pragma unroll
    for (int r = 0; r < 4; r++) {
        float4* dst = (float4*)&g_xw[(size_t)(m0 + ty * 4 + r) * HIDDEN + tx * 8];
        dst[0] = make_float4(acc[r][0], acc[r][1], acc[r][2], acc[r][3]);
        dst[1] = make_float4(acc[r][4], acc[r][5], acc[r][6], acc[r][7]);
    }
}

// ---------------------------------------------------------------------------
// K2: one CTA per batch. Stages xw[b] (200x128 f32 = 100KB) in smem, computes
//   h[j,:]  = relu((1+eps1)*xw[j,:] + sum_i adj[i,j]*xw[i,:] + b1)
//   hw[j,:] = h[j,:] @ W2                                (2 cols)
//   out[b,:] = (1/N) * sum_j hw[j,:] * ((1+eps2) + rowdeg[j]) + b2
// 8 warps x 25 rows each; lane owns 4 consecutive channels (float4).
// ---------------------------------------------------------------------------
#define CHUNK_I 25   // adjacency rows staged per step (200/25 = 8 steps)

__global__ __launch_bounds__(256, 1) void gin_fused_kernel(
    const int*   __restrict__ adj,
    const float* __restrict__ b1,
    const float* __restrict__ W2,
    const float* __restrict__ b2,
    const float* __restrict__ eps1p,
    const float* __restrict__ eps2p,
    float*       __restrict__ out)
{
    extern __shared__ float smem[];
    float* xw_s = smem;                           // 200*128 = 25600 f
    float* adjs = smem + N_NODE * HIDDEN;         // CHUNK_I*200 = 5000 f
    __shared__ float red[8][2];

    const int b    = blockIdx.x;
    const int t    = threadIdx.x;
    const int w    = t >> 5;
    const int lane = t & 31;

    const float eps1 = *eps1p;
    const float eps2 = *eps2p;
    const int* adj_b = adj + (size_t)b * N_NODE * N_NODE;

    // Phase A: stage xw[b] into smem
    {
        const float4* src = (const float4*)&g_xw[(size_t)b * N_NODE * HIDDEN];
        float4* dst = (float4*)xw_s;
        for (int i = t; i < N_NODE * HIDDEN / 4; i += 256) dst[i] = src[i];
    }

    // Phase B: agg[j,f] = sum_i adj[i,j] * xw[i,f]
    float acc[25][4];
#pragma unroll
    for (int r = 0; r < 25; r++) {
        acc[r][0] = 0.f; acc[r][1] = 0.f; acc[r][2] = 0.f; acc[r][3] = 0.f;
    }

    for (int c0 = 0; c0 < N_NODE; c0 += CHUNK_I) {
        __syncthreads();
        for (int i = t; i < CHUNK_I * N_NODE; i += 256)
            adjs[i] = (float)adj_b[c0 * N_NODE + i];   // rows c0..c0+24, contiguous
        __syncthreads();

#pragma unroll 1
        for (int ii = 0; ii < CHUNK_I; ii++) {
            const int i = c0 + ii;
            float4 xv = *(const float4*)&xw_s[i * HIDDEN + lane * 4];
            const float* arow = &adjs[ii * N_NODE];
#pragma unroll
            for (int r = 0; r < 25; r++) {
                float a = arow[w + 8 * r];             // lane-uniform broadcast
                acc[r][0] += a * xv.x;
                acc[r][1] += a * xv.y;
                acc[r][2] += a * xv.z;
                acc[r][3] += a * xv.w;
            }
        }
    }

    // Phase C: epilogue — bias+relu, project by W2, rowdeg-weighted graph sum
    const float c1 = 1.f + eps1;
    float4 b1v = *(const float4*)&b1[lane * 4];
    // W2 row-major [128,2]; lane covers channels f0..f0+3 -> 8 consecutive floats
    float4 w2a = *(const float4*)&W2[(lane * 4) * 2];       // f0:{c0,c1} f0+1:{c0,c1}
    float4 w2b = *(const float4*)&W2[(lane * 4 + 2) * 2];   // f0+2,f0+3

    float sum0 = 0.f, sum1 = 0.f;
#pragma unroll 1
    for (int r = 0; r < 25; r++) {
        const int j = w + 8 * r;
        float4 xj = *(const float4*)&xw_s[j * HIDDEN + lane * 4];
        float h0 = fmaxf(fmaf(c1, xj.x, acc[r][0]) + b1v.x, 0.f);
        float h1 = fmaxf(fmaf(c1, xj.y, acc[r][1]) + b1v.y, 0.f);
        float h2 = fmaxf(fmaf(c1, xj.z, acc[r][2]) + b1v.z, 0.f);
        float h3 = fmaxf(fmaf(c1, xj.w, acc[r][3]) + b1v.w, 0.f);
        float p0 = h0 * w2a.x + h1 * w2a.z + h2 * w2b.x + h3 * w2b.z;
        float p1 = h0 * w2a.y + h1 * w2a.w + h2 * w2b.y + h3 * w2b.w;
        // rowdeg[j] = sum of adjacency row j (coalesced global reads, L2-hot)
        int d = 0;
        for (int q = lane; q < N_NODE; q += 32) d += adj_b[j * N_NODE + q];
#pragma unroll
        for (int off = 16; off; off >>= 1) {
            p0 += __shfl_xor_sync(0xffffffffu, p0, off);
            p1 += __shfl_xor_sync(0xffffffffu, p1, off);
            d  += __shfl_xor_sync(0xffffffffu, d,  off);
        }
        float wgt = (1.f + eps2) + (float)d;
        sum0 += p0 * wgt;
        sum1 += p1 * wgt;
    }

    if (lane == 0) { red[w][0] = sum0; red[w][1] = sum1; }
    __syncthreads();
    if (t == 0) {
        float s0 = 0.f, s1 = 0.f;
#pragma unroll
        for (int q = 0; q < 8; q++) { s0 += red[q][0]; s1 += red[q][1]; }
        out[b * 2 + 0] = s0 * (1.f / N_NODE) + b2[0];
        out[b * 2 + 1] = s1 * (1.f / N_NODE) + b2[1];
    }
}

// ---------------------------------------------------------------------------
extern "C" void kernel_launch(void* const* d_in, const int* in_sizes, int n_in,
                              void* d_out, int out_size)
{
    const float* x    = (const float*)d_in[0];   // [512,200,200]
    const int*   adj  = (const int*)  d_in[1];   // [512,200,200]
    const float* W1   = (const float*)d_in[2];   // [200,128]
    const float* b1   = (const float*)d_in[3];   // [128]
    const float* W2   = (const float*)d_in[4];   // [128,2]
    const float* b2   = (const float*)d_in[5];   // [2]
    const float* eps1 = (const float*)d_in[6];
    const float* eps2 = (const float*)d_in[7];
    float* out = (float*)d_out;                  // [512,2]

    const int smem2 = (N_NODE * HIDDEN + CHUNK_I * N_NODE) * (int)sizeof(float); // 122400 B
    cudaFuncSetAttribute(gin_fused_kernel,
                         cudaFuncAttributeMaxDynamicSharedMemorySize, smem2);

    const int M = BATCH * N_NODE;                // 102400
    gemm_xw_kernel<<<M / 64, 256>>>(x, W1);
    gin_fused_kernel<<<BATCH, 256, smem2>>>(adj, b1, W2, b2, eps1, eps2, out);
}